// round 1
// baseline (speedup 1.0000x reference)
#include <cuda_runtime.h>
#include <math.h>

#define BB 64
#define SS 512
#define FF 128
#define HH 512
#define G4 2048

// Scratch (static device globals — no allocation at kernel_launch time)
__device__ float g_xg[(size_t)SS * BB * G4];    // [S][B][4H] precomputed input gates
__device__ float g_hist[(size_t)SS * BB * HH];  // [S][B][H] hidden state history
__device__ float g_h0[BB * HH];                 // zero initial hidden state
__device__ float g_c[BB * HH];                  // cell state (re-zeroed each launch)

__global__ void init_kernel() {
    int i = blockIdx.x * blockDim.x + threadIdx.x;
    if (i < BB * HH) { g_h0[i] = 0.f; g_c[i] = 0.f; }
}

// ---------------------------------------------------------------------------
// x_gates GEMM: C[m=(s,b)][g] = sum_f inputs[b,s,f] * W_ih[g,f] + b_ih[g]+b_hh[g]
// M = S*B = 32768, N = 2048, K = 128. BM=BN=64, BK=32, 256 threads, 4x4/thread.
// ---------------------------------------------------------------------------
__global__ __launch_bounds__(256) void xg_kernel(
    const float* __restrict__ inp, const float* __restrict__ Wih,
    const float* __restrict__ bih, const float* __restrict__ bhh)
{
    __shared__ float As[32][68];
    __shared__ float Bs[32][68];
    const int gBase = blockIdx.x * 64;
    const int mBase = blockIdx.y * 64;
    const int t = threadIdx.x;
    const int tx = t & 15, ty = t >> 4;

    float acc[4][4] = {};

    for (int k0 = 0; k0 < FF; k0 += 32) {
        #pragma unroll
        for (int it = 0; it < 2; it++) {
            int idx = t + it * 256;
            int row = idx >> 3, vec = idx & 7;
            int m = mBase + row;
            int b = m & 63, s = m >> 6;
            float4 v = *(const float4*)(inp + ((size_t)b * SS + s) * FF + k0 + vec * 4);
            As[vec * 4 + 0][row] = v.x; As[vec * 4 + 1][row] = v.y;
            As[vec * 4 + 2][row] = v.z; As[vec * 4 + 3][row] = v.w;
        }
        #pragma unroll
        for (int it = 0; it < 2; it++) {
            int idx = t + it * 256;
            int row = idx >> 3, vec = idx & 7;
            float4 v = *(const float4*)(Wih + (size_t)(gBase + row) * FF + k0 + vec * 4);
            Bs[vec * 4 + 0][row] = v.x; Bs[vec * 4 + 1][row] = v.y;
            Bs[vec * 4 + 2][row] = v.z; Bs[vec * 4 + 3][row] = v.w;
        }
        __syncthreads();
        #pragma unroll
        for (int kk = 0; kk < 32; kk++) {
            float a[4], b[4];
            *(float4*)a = *(const float4*)&As[kk][ty * 4];
            *(float4*)b = *(const float4*)&Bs[kk][tx * 4];
            #pragma unroll
            for (int i = 0; i < 4; i++)
                #pragma unroll
                for (int j = 0; j < 4; j++)
                    acc[i][j] += a[i] * b[j];
        }
        __syncthreads();
    }

    float bias[4];
    #pragma unroll
    for (int j = 0; j < 4; j++) {
        int g = gBase + tx * 4 + j;
        bias[j] = bih[g] + bhh[g];
    }
    #pragma unroll
    for (int i = 0; i < 4; i++) {
        int m = mBase + ty * 4 + i;
        float4 o;
        o.x = acc[i][0] + bias[0];
        o.y = acc[i][1] + bias[1];
        o.z = acc[i][2] + bias[2];
        o.w = acc[i][3] + bias[3];
        *(float4*)(g_xg + (size_t)m * G4 + gBase + tx * 4) = o;
    }
}

// ---------------------------------------------------------------------------
// One LSTM step: for its (j,b) tile each thread computes all 4 gate dots over
// K=H, adds xg, applies nonlinearities, updates c and writes h to hist[s].
// Grid (32, 4): 16 hidden units x 16 batches per block, 256 threads.
// ---------------------------------------------------------------------------
__global__ __launch_bounds__(256) void step_kernel(const float* __restrict__ Whh, int s)
{
    __shared__ float hs[16][68];
    __shared__ float ws[64][68];
    const int j0 = blockIdx.x * 16;
    const int b0 = blockIdx.y * 16;
    const int t = threadIdx.x;
    const int tx = t & 15, ty = t >> 4;

    const float* __restrict__ hprev = (s == 0) ? g_h0 : (g_hist + (size_t)(s - 1) * BB * HH);

    float a0 = 0.f, a1 = 0.f, a2 = 0.f, a3 = 0.f;

    for (int kc = 0; kc < HH; kc += 64) {
        {
            int row = t >> 4, vec = t & 15;
            *(float4*)&hs[row][vec * 4] =
                *(const float4*)(hprev + (size_t)(b0 + row) * HH + kc + vec * 4);
        }
        #pragma unroll
        for (int it = 0; it < 4; it++) {
            int idx = t + it * 256;
            int row = idx >> 4, vec = idx & 15;
            int g = row >> 4, jj = row & 15;
            *(float4*)&ws[row][vec * 4] =
                *(const float4*)(Whh + (size_t)(g * HH + j0 + jj) * HH + kc + vec * 4);
        }
        __syncthreads();
        #pragma unroll
        for (int kk = 0; kk < 64; kk += 4) {
            float hv[4], w0[4], w1[4], w2[4], w3[4];
            *(float4*)hv = *(const float4*)&hs[tx][kk];
            *(float4*)w0 = *(const float4*)&ws[ty][kk];
            *(float4*)w1 = *(const float4*)&ws[16 + ty][kk];
            *(float4*)w2 = *(const float4*)&ws[32 + ty][kk];
            *(float4*)w3 = *(const float4*)&ws[48 + ty][kk];
            #pragma unroll
            for (int q = 0; q < 4; q++) {
                a0 += hv[q] * w0[q];
                a1 += hv[q] * w1[q];
                a2 += hv[q] * w2[q];
                a3 += hv[q] * w3[q];
            }
        }
        __syncthreads();
    }

    const int b = b0 + tx, j = j0 + ty;
    const size_t xbase = ((size_t)s * BB + b) * G4 + j;
    a0 += g_xg[xbase];
    a1 += g_xg[xbase + HH];
    a2 += g_xg[xbase + 2 * HH];
    a3 += g_xg[xbase + 3 * HH];

    float ig = 1.f / (1.f + __expf(-a0));
    float fg = 1.f / (1.f + __expf(-a1));
    float gg = tanhf(a2);
    float og = 1.f / (1.f + __expf(-a3));

    const int cidx = b * HH + j;
    float c = fg * g_c[cidx] + ig * gg;
    g_c[cidx] = c;
    float h = og * tanhf(c);
    g_hist[((size_t)s * BB + b) * HH + j] = h;
}

// ---------------------------------------------------------------------------
// Output GEMM: out[b][s][f] = sum_j hist[s][b][j] * W_out[f][j] + b_out[f]
// M = S*B = 32768 (m = s*64+b), N = 128, K = 512.
// ---------------------------------------------------------------------------
__global__ __launch_bounds__(256) void out_kernel(
    const float* __restrict__ Wout, const float* __restrict__ bout,
    float* __restrict__ out)
{
    __shared__ float As[32][68];
    __shared__ float Bs[32][68];
    const int fBase = blockIdx.x * 64;
    const int mBase = blockIdx.y * 64;
    const int t = threadIdx.x;
    const int tx = t & 15, ty = t >> 4;

    float acc[4][4] = {};

    for (int k0 = 0; k0 < HH; k0 += 32) {
        #pragma unroll
        for (int it = 0; it < 2; it++) {
            int idx = t + it * 256;
            int row = idx >> 3, vec = idx & 7;
            float4 v = *(const float4*)(g_hist + (size_t)(mBase + row) * HH + k0 + vec * 4);
            As[vec * 4 + 0][row] = v.x; As[vec * 4 + 1][row] = v.y;
            As[vec * 4 + 2][row] = v.z; As[vec * 4 + 3][row] = v.w;
        }
        #pragma unroll
        for (int it = 0; it < 2; it++) {
            int idx = t + it * 256;
            int row = idx >> 3, vec = idx & 7;
            float4 v = *(const float4*)(Wout + (size_t)(fBase + row) * HH + k0 + vec * 4);
            Bs[vec * 4 + 0][row] = v.x; Bs[vec * 4 + 1][row] = v.y;
            Bs[vec * 4 + 2][row] = v.z; Bs[vec * 4 + 3][row] = v.w;
        }
        __syncthreads();
        #pragma unroll
        for (int kk = 0; kk < 32; kk++) {
            float a[4], b[4];
            *(float4*)a = *(const float4*)&As[kk][ty * 4];
            *(float4*)b = *(const float4*)&Bs[kk][tx * 4];
            #pragma unroll
            for (int i = 0; i < 4; i++)
                #pragma unroll
                for (int j = 0; j < 4; j++)
                    acc[i][j] += a[i] * b[j];
        }
        __syncthreads();
    }

    float bias[4];
    #pragma unroll
    for (int j = 0; j < 4; j++) bias[j] = bout[fBase + tx * 4 + j];

    #pragma unroll
    for (int i = 0; i < 4; i++) {
        int m = mBase + ty * 4 + i;
        int b = m & 63, s = m >> 6;
        float4 o;
        o.x = acc[i][0] + bias[0];
        o.y = acc[i][1] + bias[1];
        o.z = acc[i][2] + bias[2];
        o.w = acc[i][3] + bias[3];
        *(float4*)(out + ((size_t)b * SS + s) * FF + fBase + tx * 4) = o;
    }
}

extern "C" void kernel_launch(void* const* d_in, const int* in_sizes, int n_in,
                              void* d_out, int out_size)
{
    const float* inp  = (const float*)d_in[0];
    const float* Wih  = (const float*)d_in[1];
    const float* Whh  = (const float*)d_in[2];
    const float* bih  = (const float*)d_in[3];
    const float* bhh  = (const float*)d_in[4];
    const float* Wout = (const float*)d_in[5];
    const float* bout = (const float*)d_in[6];
    float* out = (float*)d_out;

    init_kernel<<<(BB * HH + 255) / 256, 256>>>();
    xg_kernel<<<dim3(G4 / 64, (SS * BB) / 64), 256>>>(inp, Wih, bih, bhh);
    for (int s = 0; s < SS; s++)
        step_kernel<<<dim3(HH / 16, BB / 16), 256>>>(Whh, s);
    out_kernel<<<dim3(FF / 64, (SS * BB) / 64), 256>>>(Wout, bout, out);
}